// round 14
// baseline (speedup 1.0000x reference)
#include <cuda_runtime.h>
#include <cuda_bf16.h>
#include <math.h>

// ---------------------------------------------------------------------------
// AttentionClassificationHead — GB300, round 14
// R13 skeleton (16 windows/CTA, 2048 CTAs, 2 CTAs/SM, constants staged) +
// (1) B tile-0 prefetch hoisted before each preceding barrier,
// (2) final w2-dot fused into GEMM3 epilogue (one pass + one barrier saved).
// B=64, N=512, T=6, E=256, H=4, hd=64, BN=32768
// ---------------------------------------------------------------------------

__device__ float g_qs[256];          // q = query @ Wq^T + bq
__device__ float g_weff[1024];       // [4][256]
__device__ float g_ceff[4];
// uint4 = (hi_k2=kt*8+t, hi_k2=kt*8+t+4, lo_t, lo_t+4) per (col, kt)
__device__ uint4 g_B1[16384];        // 256 cols (4 heads x 64)
__device__ uint4 g_B2[16384];        // 256 cols
__device__ uint4 g_B3[8192];         // 128 cols

// Shared memory float offsets (16 windows)
#define W0    0             // 1028: weff + ceff
#define BI0   1056          // 1312: staged constants
//   [0:256) bv  [256:512) out_b  [512:640) b1  [640:768) w2
//   [768:1024) ln_g  [1024:1280) ln_b  [1280] b2
#define XAH0  2368          // hi plane u32 [16][516] = 8256
#define XAL0  10624         // lo plane u32 [16][516] = 8256
#define BB0   2368          // fp32 [16][264] = 4224 (aliases XAH, post-GEMM2)
#define BAH0  18880         // hi plane u32 [16][132] = 2112
#define BAL0  20992         // lo plane u32 [16][132] = 2112
#define MB0   23104         // 16 ints
#define PD0   23120         // 128 floats: fused-dot partials [16 rows][8 warps]
#define SFLOATS 23248
#define SMEM_BYTES (SFLOATS * 4)     // 92992 B -> 2 CTAs/SM
#define XSTH 516            // plane row stride (u32); 2064B, mod128=16
#define BAST 132            // BA plane row stride (u32); 528B, mod128=16
#define BBST 264            // fp32 buf stride

__device__ __forceinline__ float gelu_exact(float v) {
    return 0.5f * v * (1.0f + erff(v * 0.70710678118654752f));
}

// rn split of (a,b) into (hi bf16x2, lo bf16x2); low half = a (even k)
__device__ __forceinline__ uint2 split_pack2(float a, float b) {
    unsigned hi, lo;
    asm("cvt.rn.bf16x2.f32 %0, %1, %2;" : "=r"(hi) : "f"(b), "f"(a));
    float la = a - __uint_as_float(hi << 16);
    float lb = b - __uint_as_float(hi & 0xffff0000u);
    asm("cvt.rn.bf16x2.f32 %0, %1, %2;" : "=r"(lo) : "f"(lb), "f"(la));
    return make_uint2(hi, lo);
}

__device__ __forceinline__ void mma16816(float* c, const unsigned* a,
                                         unsigned b0, unsigned b1) {
    asm("mma.sync.aligned.m16n8k16.row.col.f32.bf16.bf16.f32 "
        "{%0,%1,%2,%3}, {%4,%5,%6,%7}, {%8,%9}, {%0,%1,%2,%3};"
        : "+f"(c[0]), "+f"(c[1]), "+f"(c[2]), "+f"(c[3])
        : "r"(a[0]), "r"(a[1]), "r"(a[2]), "r"(a[3]), "r"(b0), "r"(b1));
}

__device__ __forceinline__ void ldsm4(unsigned* r, unsigned addr) {
    asm volatile(
        "ldmatrix.sync.aligned.m8n8.x4.shared.b16 {%0,%1,%2,%3}, [%4];"
        : "=r"(r[0]), "=r"(r[1]), "=r"(r[2]), "=r"(r[3]) : "r"(addr));
}

__device__ __forceinline__ unsigned sm_u32(const void* p) {
    return (unsigned)__cvta_generic_to_shared(p);
}

// ---------------------------------------------------------------------------
// prepA (192 blocks x 256): blocks 0-159 fragment-pack the three weight
// matrices; blocks 160-191 compute q rows (warp per row).
// ---------------------------------------------------------------------------
__global__ void ach_prepA(const float* __restrict__ query,
                          const float* __restrict__ ipw,
                          const float* __restrict__ ipb,
                          const float* __restrict__ outw,
                          const float* __restrict__ w1) {
    if (blockIdx.x < 160) {
        int idx = blockIdx.x * 256 + threadIdx.x;   // 0..40959
        const float* base;
        uint4* dst;
        int j;
        if (idx < 16384)      { j = idx;         base = ipw + 512 * 256; dst = g_B1; }
        else if (idx < 32768) { j = idx - 16384; base = outw;            dst = g_B2; }
        else                  { j = idx - 32768; base = w1;              dst = g_B3; }
        int t = j & 3, cc = (j >> 2) & 7, kt = (j >> 5) & 15, cg = j >> 9;
        int col = cg * 8 + cc;
        int kA = kt * 16 + 2 * t;
        const float* row = base + col * 256;
        uint2 p = split_pack2(row[kA],     row[kA + 1]);
        uint2 q = split_pack2(row[kA + 8], row[kA + 9]);
        dst[j] = make_uint4(p.x, q.x, p.y, q.y);
    } else {
        const int row = (blockIdx.x - 160) * 8 + (threadIdx.x >> 5);
        const int lane = threadIdx.x & 31;
        const float4* rp = (const float4*)(ipw + row * 256);
        const float4* qp = (const float4*)query;
        float s = 0.f;
#pragma unroll
        for (int j = 0; j < 2; j++) {
            float4 a = rp[lane * 2 + j];
            float4 q = qp[lane * 2 + j];
            s += a.x * q.x + a.y * q.y + a.z * q.z + a.w * q.w;
        }
#pragma unroll
        for (int o = 16; o > 0; o >>= 1)
            s += __shfl_xor_sync(0xffffffffu, s, o);
        if (lane == 0) g_qs[row] = s + ipb[row];
    }
}

// ---------------------------------------------------------------------------
// prepB (4 blocks x 256): weff[h][e] + ceff[h], block per head.
// ---------------------------------------------------------------------------
__global__ void ach_prepB(const float* __restrict__ ipw,
                          const float* __restrict__ ipb) {
    __shared__ float qs[64];
    const int h = blockIdx.x;
    const int e = threadIdx.x;
    if (e < 64) qs[e] = g_qs[h * 64 + e];
    __syncthreads();
    const float* wp = ipw + (256 + h * 64) * 256 + e;
    float s = 0.f;
#pragma unroll 8
    for (int d = 0; d < 64; d++)
        s += qs[d] * wp[d * 256];
    g_weff[h * 256 + e] = s;
    if (e == 0) {
        float c = 0.f;
        for (int d = 0; d < 64; d++) c += qs[d] * ipb[256 + h * 64 + d];
        g_ceff[h] = c;
    }
}

// ---------------------------------------------------------------------------
// MMA GEMM: per warp M=16 x NT*8 cols x K=256. A fragments register
// double-buffered via ldmatrix.x4 from planar hi/lo smem; B uint4 from L2,
// depth-2 ring; tile 0 (pre[]) loaded by CALLER before the preceding barrier.
// OM: 0 = fp32 out, 1 = planar split out, 3 = gelu + fused w2 dot -> pd.
// ---------------------------------------------------------------------------
template <int NT, int OM>
__device__ __forceinline__ void gemm_mma(unsigned aHi, unsigned aLo,
                                         const uint4* __restrict__ bp,
                                         const uint4* pre,
                                         const float* bias, int outcol0,
                                         float* outf, int ofst,
                                         unsigned* outHi, unsigned* outLo,
                                         int ost, const float* w2s,
                                         float* pd) {
    const int lane = threadIdx.x & 31;
    const int g = lane >> 2, t = lane & 3;

    float acc[NT][4];
#pragma unroll
    for (int nt = 0; nt < NT; nt++) {
        float b0 = bias[outcol0 + nt * 8 + 2 * t];
        float b1 = bias[outcol0 + nt * 8 + 2 * t + 1];
        acc[nt][0] = b0; acc[nt][1] = b1; acc[nt][2] = b0; acc[nt][3] = b1;
    }

    uint4 Bb[2][NT];
#pragma unroll
    for (int nt = 0; nt < NT; nt++) Bb[0][nt] = pre[nt];

    unsigned Ah[2][4], Al[2][4];
    ldsm4(Ah[0], aHi);
    ldsm4(Al[0], aLo);

#pragma unroll
    for (int kt = 0; kt < 16; kt++) {
        if (kt + 1 < 16) {
            ldsm4(Ah[(kt + 1) & 1], aHi + (kt + 1) * 32);
            ldsm4(Al[(kt + 1) & 1], aLo + (kt + 1) * 32);
#pragma unroll
            for (int nt = 0; nt < NT; nt++)
                Bb[(kt + 1) & 1][nt] = __ldg(bp + (kt + 1) * 32 + nt * 512);
        }
#pragma unroll
        for (int nt = 0; nt < NT; nt++) {
            uint4 v = Bb[kt & 1][nt];
            mma16816(acc[nt], Ah[kt & 1], v.x, v.y);
            mma16816(acc[nt], Ah[kt & 1], v.z, v.w);
            mma16816(acc[nt], Al[kt & 1], v.x, v.y);
        }
    }

    if (OM == 3) {
        // gelu + fused partial dot with w2 (smem), reduce over t-lanes
        float pr0 = 0.f, pr1 = 0.f;
#pragma unroll
        for (int nt = 0; nt < NT; nt++) {
            int col = outcol0 + nt * 8 + 2 * t;
            float wa = w2s[col], wb = w2s[col + 1];
            pr0 += gelu_exact(acc[nt][0]) * wa + gelu_exact(acc[nt][1]) * wb;
            pr1 += gelu_exact(acc[nt][2]) * wa + gelu_exact(acc[nt][3]) * wb;
        }
        pr0 += __shfl_xor_sync(0xffffffffu, pr0, 1);
        pr0 += __shfl_xor_sync(0xffffffffu, pr0, 2);
        pr1 += __shfl_xor_sync(0xffffffffu, pr1, 1);
        pr1 += __shfl_xor_sync(0xffffffffu, pr1, 2);
        if (t == 0) {
            const int wd = threadIdx.x >> 5;
            pd[g * 8 + wd] = pr0;
            pd[(g + 8) * 8 + wd] = pr1;
        }
        return;
    }

#pragma unroll
    for (int nt = 0; nt < NT; nt++) {
        float c0 = acc[nt][0], c1 = acc[nt][1];
        float c2 = acc[nt][2], c3 = acc[nt][3];
        int r0 = g, r1 = g + 8;
        if (OM == 1) {
            int k2o = (outcol0 >> 1) + nt * 4 + t;
            uint2 s0 = split_pack2(c0, c1);
            uint2 s1 = split_pack2(c2, c3);
            outHi[r0 * ost + k2o] = s0.x;
            outLo[r0 * ost + k2o] = s0.y;
            outHi[r1 * ost + k2o] = s1.x;
            outLo[r1 * ost + k2o] = s1.y;
        } else {
            int col = outcol0 + nt * 8 + 2 * t;
            *(float2*)&outf[r0 * ofst + col] = make_float2(c0, c1);
            *(float2*)&outf[r1 * ofst + col] = make_float2(c2, c3);
        }
    }
}

// ---------------------------------------------------------------------------
// Main kernel: 2048 CTAs x 256 threads, 16 windows per CTA, 2 CTAs/SM.
// ---------------------------------------------------------------------------
__global__ void __launch_bounds__(256, 2)
ach_main(const float* __restrict__ x, const int* __restrict__ mask,
         const float* __restrict__ ipb, const float* __restrict__ out_b,
         const float* __restrict__ ln_g, const float* __restrict__ ln_b,
         const float* __restrict__ b1, const float* __restrict__ w2,
         const float* __restrict__ b2, float* __restrict__ out) {
    extern __shared__ float S[];
    unsigned* XH = (unsigned*)&S[XAH0];
    unsigned* XL = (unsigned*)&S[XAL0];
    unsigned* BH = (unsigned*)&S[BAH0];
    unsigned* BL = (unsigned*)&S[BAL0];
    const int tid = threadIdx.x;
    const int lane = tid & 31;
    const int wid = tid >> 5;      // 0..7 = n-group
    const int bn0 = blockIdx.x << 4;

    // ---- stage weff/ceff + all epilogue constants into smem ----
    for (int i = tid; i < 1024; i += 256) S[W0 + i] = g_weff[i];
    if (tid < 4) S[W0 + 1024 + tid] = g_ceff[tid];
    S[BI0 + tid]       = ipb[512 + tid];    // bv
    S[BI0 + 256 + tid] = out_b[tid];
    if (tid < 128) {
        S[BI0 + 512 + tid] = b1[tid];
        S[BI0 + 640 + tid] = w2[tid];
    }
    S[BI0 + 768 + tid]  = ln_g[tid];
    S[BI0 + 1024 + tid] = ln_b[tid];
    if (tid == 0) S[BI0 + 1280] = b2[0];

    // ---- prefetch GEMM1's B tile 0 (independent of activations) ----
    const uint4* bp1 = g_B1 + (size_t)(wid * 4) * 512 + lane;
    uint4 pre1[4];
#pragma unroll
    for (int nt = 0; nt < 4; nt++) pre1[nt] = __ldg(bp1 + nt * 512);
    __syncthreads();

    // ---- Phase 1: 2 windows per warp — scores, softmax, xbar (planar) ----
#pragma unroll
    for (int rep = 0; rep < 2; rep++) {
        const int w = wid * 2 + rep;
        const long bn = (long)bn0 + w;
        const float4* xp = (const float4*)(x + bn * 1536);
        float4 xa[6], xc[6];
#pragma unroll
        for (int t = 0; t < 6; t++) {
            xa[t] = xp[t * 64 + lane];
            xc[t] = xp[t * 64 + 32 + lane];
        }
        int mv = (lane < 6) ? mask[bn * 6 + lane] : 0;
        unsigned mb = __ballot_sync(0xffffffffu, mv != 0) & 0x3fu;
        if (lane == 0) ((int*)S)[MB0 + w] = (int)mb;

        float aw[4][6];
#pragma unroll
        for (int h = 0; h < 4; h++) {
            const float4* wf = (const float4*)&S[W0 + h * 256];
            float4 wa = wf[lane], wc = wf[32 + lane];
            float ce = S[W0 + 1024 + h];
            float sc[6];
#pragma unroll
            for (int t = 0; t < 6; t++) {
                float p = xa[t].x * wa.x + xa[t].y * wa.y + xa[t].z * wa.z +
                          xa[t].w * wa.w + xc[t].x * wc.x + xc[t].y * wc.y +
                          xc[t].z * wc.z + xc[t].w * wc.w;
#pragma unroll
                for (int o = 16; o > 0; o >>= 1)
                    p += __shfl_xor_sync(0xffffffffu, p, o);
                sc[t] = ((mb >> t) & 1u) ? (p + ce) * 0.125f : -1e9f;
            }
            float m = sc[0];
#pragma unroll
            for (int t = 1; t < 6; t++) m = fmaxf(m, sc[t]);
            float s = 0.f;
#pragma unroll
            for (int t = 0; t < 6; t++) { aw[h][t] = expf(sc[t] - m); s += aw[h][t]; }
            float inv = 1.0f / s;
#pragma unroll
            for (int t = 0; t < 6; t++) aw[h][t] *= inv;
        }
#pragma unroll
        for (int h = 0; h < 4; h++) {
            float4 A = make_float4(0.f, 0.f, 0.f, 0.f);
            float4 C = make_float4(0.f, 0.f, 0.f, 0.f);
#pragma unroll
            for (int t = 0; t < 6; t++) {
                float a = aw[h][t];
                A.x += a * xa[t].x; A.y += a * xa[t].y;
                A.z += a * xa[t].z; A.w += a * xa[t].w;
                C.x += a * xc[t].x; C.y += a * xc[t].y;
                C.z += a * xc[t].z; C.w += a * xc[t].w;
            }
            uint2 p0 = split_pack2(A.x, A.y), p1 = split_pack2(A.z, A.w);
            uint2 p2 = split_pack2(C.x, C.y), p3 = split_pack2(C.z, C.w);
            int o = w * XSTH + h * 128 + 2 * lane;
            *(uint2*)&XH[o]      = make_uint2(p0.x, p1.x);
            *(uint2*)&XH[o + 64] = make_uint2(p2.x, p3.x);
            *(uint2*)&XL[o]      = make_uint2(p0.y, p1.y);
            *(uint2*)&XL[o + 64] = make_uint2(p2.y, p3.y);
        }
    }
    __syncthreads();

    const int arow = lane & 15;
    const unsigned chunk = ((lane >> 4) & 1) * 16;   // bytes

    // ---- prefetch GEMM2's B tile 0, then GEMM1 ----
    const uint4* bp2 = g_B2 + (size_t)(wid * 4) * 512 + lane;
    uint4 pre2[4];
#pragma unroll
    for (int nt = 0; nt < 4; nt++) pre2[nt] = __ldg(bp2 + nt * 512);
    {
        const int h = wid >> 1;
        unsigned aHi = sm_u32(XH + arow * XSTH + h * 128) + chunk;
        unsigned aLo = sm_u32(XL + arow * XSTH + h * 128) + chunk;
        gemm_mma<4, 1>(aHi, aLo, bp1, pre1, &S[BI0], wid * 32,
                       nullptr, 0, BH, BL, BAST, nullptr, nullptr);
    }
    __syncthreads();

    // ---- prefetch GEMM3's B tile 0, then GEMM2 ----
    const uint4* bp3 = g_B3 + (size_t)(wid * 2) * 512 + lane;
    uint4 pre3[2];
#pragma unroll
    for (int nt = 0; nt < 2; nt++) pre3[nt] = __ldg(bp3 + nt * 512);
    {
        unsigned aHi = sm_u32(BH + arow * BAST) + chunk;
        unsigned aLo = sm_u32(BL + arow * BAST) + chunk;
        gemm_mma<4, 0>(aHi, aLo, bp2, pre2, &S[BI0 + 256], wid * 32,
                       &S[BB0], BBST, nullptr, nullptr, 0, nullptr, nullptr);
    }
    __syncthreads();

    // ---- LayerNorm: bufB fp32 -> bufA (planar). Lane owns 8 consecutive ----
#pragma unroll
    for (int rep = 0; rep < 2; rep++) {
        const int w = wid * 2 + rep;
        float4 va = *(const float4*)&S[BB0 + w * BBST + lane * 8];
        float4 vb = *(const float4*)&S[BB0 + w * BBST + lane * 8 + 4];
        float s = va.x + va.y + va.z + va.w + vb.x + vb.y + vb.z + vb.w;
        float s2 = va.x * va.x + va.y * va.y + va.z * va.z + va.w * va.w +
                   vb.x * vb.x + vb.y * vb.y + vb.z * vb.z + vb.w * vb.w;
#pragma unroll
        for (int o = 16; o > 0; o >>= 1) {
            s  += __shfl_xor_sync(0xffffffffu, s, o);
            s2 += __shfl_xor_sync(0xffffffffu, s2, o);
        }
        float mu = s * (1.0f / 256.0f);
        float var = s2 * (1.0f / 256.0f) - mu * mu;
        float rstd = rsqrtf(var + 1e-5f);
        float y[8];
        float vv[8] = {va.x, va.y, va.z, va.w, vb.x, vb.y, vb.z, vb.w};
#pragma unroll
        for (int j = 0; j < 8; j++) {
            int o = lane * 8 + j;
            y[j] = (vv[j] - mu) * rstd * S[BI0 + 768 + o] + S[BI0 + 1024 + o];
        }
        uint2 p0 = split_pack2(y[0], y[1]), p1 = split_pack2(y[2], y[3]);
        uint2 p2 = split_pack2(y[4], y[5]), p3 = split_pack2(y[6], y[7]);
        *(uint4*)&BH[w * BAST + lane * 4] = make_uint4(p0.x, p1.x, p2.x, p3.x);
        *(uint4*)&BL[w * BAST + lane * 4] = make_uint4(p0.y, p1.y, p2.y, p3.y);
    }
    __syncthreads();

    // ---- GEMM3: fc1 + exact GELU + fused w2 dot -> PD partials ----
    {
        unsigned aHi = sm_u32(BH + arow * BAST) + chunk;
        unsigned aLo = sm_u32(BL + arow * BAST) + chunk;
        gemm_mma<2, 3>(aHi, aLo, bp3, pre3, &S[BI0 + 512], wid * 16,
                       nullptr, 0, nullptr, nullptr, 0,
                       &S[BI0 + 640], &S[PD0]);
    }
    __syncthreads();

    // ---- Final: reduce 8 warp-partials per window, mask, store ----
#pragma unroll
    for (int rep = 0; rep < 2; rep++) {
        const int w = wid * 2 + rep;
        float v = (lane < 8) ? S[PD0 + w * 8 + lane] : 0.f;
        v += __shfl_xor_sync(0xffffffffu, v, 4);
        v += __shfl_xor_sync(0xffffffffu, v, 2);
        v += __shfl_xor_sync(0xffffffffu, v, 1);
        if (lane == 0) {
            int mb = ((int*)S)[MB0 + w];
            out[bn0 + w] = mb ? (v + S[BI0 + 1280]) : 0.0f;
        }
    }
}

// ---------------------------------------------------------------------------
extern "C" void kernel_launch(void* const* d_in, const int* in_sizes, int n_in,
                              void* d_out, int out_size) {
    (void)in_sizes; (void)n_in; (void)out_size;
    const float* x    = (const float*)d_in[0];
    const int*   mask = (const int*)d_in[1];
    const float* query= (const float*)d_in[2];
    const float* ipw  = (const float*)d_in[3];
    const float* ipb  = (const float*)d_in[4];
    const float* outw = (const float*)d_in[5];
    const float* outb = (const float*)d_in[6];
    const float* ln_g = (const float*)d_in[7];
    const float* ln_b = (const float*)d_in[8];
    const float* w1   = (const float*)d_in[9];
    const float* b1   = (const float*)d_in[10];
    const float* w2   = (const float*)d_in[11];
    const float* b2   = (const float*)d_in[12];
    float* out = (float*)d_out;

    cudaFuncSetAttribute(ach_main, cudaFuncAttributeMaxDynamicSharedMemorySize,
                         SMEM_BYTES);

    ach_prepA<<<192, 256>>>(query, ipw, ipb, outw, w1);
    ach_prepB<<<4, 256>>>(ipw, ipb);
    ach_main<<<2048, 256, SMEM_BYTES>>>(x, mask, ipb, outb, ln_g, ln_b, b1, w2,
                                        b2, out);
}

// round 15
// speedup vs baseline: 1.0359x; 1.0359x over previous
#include <cuda_runtime.h>
#include <cuda_bf16.h>
#include <math.h>

// ---------------------------------------------------------------------------
// AttentionClassificationHead — GB300, round 15
// Exactly R13 (best measured: 148.0us) + B tile-0 prefetch for GEMM2/GEMM3
// ONLY (held in GEMM-phase register slack; R14's GEMM1 prefetch lived across
// register-heavy phase-1 and regressed). Final dot un-fused (bit-exact R13).
// B=64, N=512, T=6, E=256, H=4, hd=64, BN=32768
// ---------------------------------------------------------------------------

__device__ float g_qs[256];          // q = query @ Wq^T + bq
__device__ float g_weff[1024];       // [4][256]
__device__ float g_ceff[4];
// uint4 = (hi_k2=kt*8+t, hi_k2=kt*8+t+4, lo_t, lo_t+4) per (col, kt)
__device__ uint4 g_B1[16384];        // 256 cols (4 heads x 64)
__device__ uint4 g_B2[16384];        // 256 cols
__device__ uint4 g_B3[8192];         // 128 cols

// Shared memory float offsets (16 windows)
#define W0    0             // 1028: weff + ceff
#define BI0   1056          // 1312: staged constants
//   [0:256) bv  [256:512) out_b  [512:640) b1  [640:768) w2
//   [768:1024) ln_g  [1024:1280) ln_b  [1280] b2
#define XAH0  2368          // hi plane u32 [16][516] = 8256
#define XAL0  10624         // lo plane u32 [16][516] = 8256
#define BB0   2368          // fp32 [16][264] = 4224 (aliases XAH, post-GEMM2)
#define G30   2368          // fp32 [16][136] = 2176 (aliases, post-GEMM3)
#define BAH0  18880         // hi plane u32 [16][132] = 2112
#define BAL0  20992         // lo plane u32 [16][132] = 2112
#define MB0   23104         // 16 ints
#define SFLOATS 23120
#define SMEM_BYTES (SFLOATS * 4)     // 92480 B -> 2 CTAs/SM
#define XSTH 516            // plane row stride (u32); 2064B, mod128=16
#define BAST 132            // BA plane row stride (u32); 528B, mod128=16
#define BBST 264            // fp32 buf stride
#define G3ST 136            // fp32

__device__ __forceinline__ float gelu_exact(float v) {
    return 0.5f * v * (1.0f + erff(v * 0.70710678118654752f));
}

// rn split of (a,b) into (hi bf16x2, lo bf16x2); low half = a (even k)
__device__ __forceinline__ uint2 split_pack2(float a, float b) {
    unsigned hi, lo;
    asm("cvt.rn.bf16x2.f32 %0, %1, %2;" : "=r"(hi) : "f"(b), "f"(a));
    float la = a - __uint_as_float(hi << 16);
    float lb = b - __uint_as_float(hi & 0xffff0000u);
    asm("cvt.rn.bf16x2.f32 %0, %1, %2;" : "=r"(lo) : "f"(lb), "f"(la));
    return make_uint2(hi, lo);
}

__device__ __forceinline__ void mma16816(float* c, const unsigned* a,
                                         unsigned b0, unsigned b1) {
    asm("mma.sync.aligned.m16n8k16.row.col.f32.bf16.bf16.f32 "
        "{%0,%1,%2,%3}, {%4,%5,%6,%7}, {%8,%9}, {%0,%1,%2,%3};"
        : "+f"(c[0]), "+f"(c[1]), "+f"(c[2]), "+f"(c[3])
        : "r"(a[0]), "r"(a[1]), "r"(a[2]), "r"(a[3]), "r"(b0), "r"(b1));
}

__device__ __forceinline__ void ldsm4(unsigned* r, unsigned addr) {
    asm volatile(
        "ldmatrix.sync.aligned.m8n8.x4.shared.b16 {%0,%1,%2,%3}, [%4];"
        : "=r"(r[0]), "=r"(r[1]), "=r"(r[2]), "=r"(r[3]) : "r"(addr));
}

__device__ __forceinline__ unsigned sm_u32(const void* p) {
    return (unsigned)__cvta_generic_to_shared(p);
}

// ---------------------------------------------------------------------------
// prepA (192 blocks x 256): blocks 0-159 fragment-pack the three weight
// matrices; blocks 160-191 compute q rows (warp per row).
// ---------------------------------------------------------------------------
__global__ void ach_prepA(const float* __restrict__ query,
                          const float* __restrict__ ipw,
                          const float* __restrict__ ipb,
                          const float* __restrict__ outw,
                          const float* __restrict__ w1) {
    if (blockIdx.x < 160) {
        int idx = blockIdx.x * 256 + threadIdx.x;   // 0..40959
        const float* base;
        uint4* dst;
        int j;
        if (idx < 16384)      { j = idx;         base = ipw + 512 * 256; dst = g_B1; }
        else if (idx < 32768) { j = idx - 16384; base = outw;            dst = g_B2; }
        else                  { j = idx - 32768; base = w1;              dst = g_B3; }
        int t = j & 3, cc = (j >> 2) & 7, kt = (j >> 5) & 15, cg = j >> 9;
        int col = cg * 8 + cc;
        int kA = kt * 16 + 2 * t;
        const float* row = base + col * 256;
        uint2 p = split_pack2(row[kA],     row[kA + 1]);
        uint2 q = split_pack2(row[kA + 8], row[kA + 9]);
        dst[j] = make_uint4(p.x, q.x, p.y, q.y);
    } else {
        const int row = (blockIdx.x - 160) * 8 + (threadIdx.x >> 5);
        const int lane = threadIdx.x & 31;
        const float4* rp = (const float4*)(ipw + row * 256);
        const float4* qp = (const float4*)query;
        float s = 0.f;
#pragma unroll
        for (int j = 0; j < 2; j++) {
            float4 a = rp[lane * 2 + j];
            float4 q = qp[lane * 2 + j];
            s += a.x * q.x + a.y * q.y + a.z * q.z + a.w * q.w;
        }
#pragma unroll
        for (int o = 16; o > 0; o >>= 1)
            s += __shfl_xor_sync(0xffffffffu, s, o);
        if (lane == 0) g_qs[row] = s + ipb[row];
    }
}

// ---------------------------------------------------------------------------
// prepB (4 blocks x 256): weff[h][e] + ceff[h], block per head.
// ---------------------------------------------------------------------------
__global__ void ach_prepB(const float* __restrict__ ipw,
                          const float* __restrict__ ipb) {
    __shared__ float qs[64];
    const int h = blockIdx.x;
    const int e = threadIdx.x;
    if (e < 64) qs[e] = g_qs[h * 64 + e];
    __syncthreads();
    const float* wp = ipw + (256 + h * 64) * 256 + e;
    float s = 0.f;
#pragma unroll 8
    for (int d = 0; d < 64; d++)
        s += qs[d] * wp[d * 256];
    g_weff[h * 256 + e] = s;
    if (e == 0) {
        float c = 0.f;
        for (int d = 0; d < 64; d++) c += qs[d] * ipb[256 + h * 64 + d];
        g_ceff[h] = c;
    }
}

// ---------------------------------------------------------------------------
// MMA GEMM: per warp M=16 x NT*8 cols x K=256. A fragments register
// double-buffered via ldmatrix.x4 from planar hi/lo smem; B uint4 from L2,
// depth-2 ring. If PRE, tile 0 comes from caller (prefetched before the
// preceding barrier); else loaded here.
// OM: 0 = fp32 out, 1 = planar split out, 2 = gelu fp32 out.
// ---------------------------------------------------------------------------
template <int NT, int OM, bool PRE>
__device__ __forceinline__ void gemm_mma(unsigned aHi, unsigned aLo,
                                         const uint4* __restrict__ bp,
                                         const uint4* pre,
                                         const float* bias, int outcol0,
                                         float* outf, int ofst,
                                         unsigned* outHi, unsigned* outLo,
                                         int ost) {
    const int lane = threadIdx.x & 31;
    const int g = lane >> 2, t = lane & 3;

    float acc[NT][4];
#pragma unroll
    for (int nt = 0; nt < NT; nt++) {
        float b0 = bias[outcol0 + nt * 8 + 2 * t];
        float b1 = bias[outcol0 + nt * 8 + 2 * t + 1];
        acc[nt][0] = b0; acc[nt][1] = b1; acc[nt][2] = b0; acc[nt][3] = b1;
    }

    uint4 Bb[2][NT];
#pragma unroll
    for (int nt = 0; nt < NT; nt++)
        Bb[0][nt] = PRE ? pre[nt] : __ldg(bp + nt * 512);

    unsigned Ah[2][4], Al[2][4];
    ldsm4(Ah[0], aHi);
    ldsm4(Al[0], aLo);

#pragma unroll
    for (int kt = 0; kt < 16; kt++) {
        if (kt + 1 < 16) {
            ldsm4(Ah[(kt + 1) & 1], aHi + (kt + 1) * 32);
            ldsm4(Al[(kt + 1) & 1], aLo + (kt + 1) * 32);
#pragma unroll
            for (int nt = 0; nt < NT; nt++)
                Bb[(kt + 1) & 1][nt] = __ldg(bp + (kt + 1) * 32 + nt * 512);
        }
#pragma unroll
        for (int nt = 0; nt < NT; nt++) {
            uint4 v = Bb[kt & 1][nt];
            mma16816(acc[nt], Ah[kt & 1], v.x, v.y);
            mma16816(acc[nt], Ah[kt & 1], v.z, v.w);
            mma16816(acc[nt], Al[kt & 1], v.x, v.y);
        }
    }

#pragma unroll
    for (int nt = 0; nt < NT; nt++) {
        float c0 = acc[nt][0], c1 = acc[nt][1];
        float c2 = acc[nt][2], c3 = acc[nt][3];
        int r0 = g, r1 = g + 8;
        if (OM == 1) {
            int k2o = (outcol0 >> 1) + nt * 4 + t;
            uint2 s0 = split_pack2(c0, c1);
            uint2 s1 = split_pack2(c2, c3);
            outHi[r0 * ost + k2o] = s0.x;
            outLo[r0 * ost + k2o] = s0.y;
            outHi[r1 * ost + k2o] = s1.x;
            outLo[r1 * ost + k2o] = s1.y;
        } else {
            if (OM == 2) {
                c0 = gelu_exact(c0); c1 = gelu_exact(c1);
                c2 = gelu_exact(c2); c3 = gelu_exact(c3);
            }
            int col = outcol0 + nt * 8 + 2 * t;
            *(float2*)&outf[r0 * ofst + col] = make_float2(c0, c1);
            *(float2*)&outf[r1 * ofst + col] = make_float2(c2, c3);
        }
    }
}

// ---------------------------------------------------------------------------
// Main kernel: 2048 CTAs x 256 threads, 16 windows per CTA, 2 CTAs/SM.
// ---------------------------------------------------------------------------
__global__ void __launch_bounds__(256, 2)
ach_main(const float* __restrict__ x, const int* __restrict__ mask,
         const float* __restrict__ ipb, const float* __restrict__ out_b,
         const float* __restrict__ ln_g, const float* __restrict__ ln_b,
         const float* __restrict__ b1, const float* __restrict__ w2,
         const float* __restrict__ b2, float* __restrict__ out) {
    extern __shared__ float S[];
    unsigned* XH = (unsigned*)&S[XAH0];
    unsigned* XL = (unsigned*)&S[XAL0];
    unsigned* BH = (unsigned*)&S[BAH0];
    unsigned* BL = (unsigned*)&S[BAL0];
    const int tid = threadIdx.x;
    const int lane = tid & 31;
    const int wid = tid >> 5;      // 0..7 = n-group
    const int bn0 = blockIdx.x << 4;

    // ---- stage weff/ceff + all epilogue constants into smem ----
    for (int i = tid; i < 1024; i += 256) S[W0 + i] = g_weff[i];
    if (tid < 4) S[W0 + 1024 + tid] = g_ceff[tid];
    S[BI0 + tid]       = ipb[512 + tid];    // bv
    S[BI0 + 256 + tid] = out_b[tid];
    if (tid < 128) {
        S[BI0 + 512 + tid] = b1[tid];
        S[BI0 + 640 + tid] = w2[tid];
    }
    S[BI0 + 768 + tid]  = ln_g[tid];
    S[BI0 + 1024 + tid] = ln_b[tid];
    if (tid == 0) S[BI0 + 1280] = b2[0];
    __syncthreads();

    // ---- Phase 1: 2 windows per warp — scores, softmax, xbar (planar) ----
#pragma unroll
    for (int rep = 0; rep < 2; rep++) {
        const int w = wid * 2 + rep;
        const long bn = (long)bn0 + w;
        const float4* xp = (const float4*)(x + bn * 1536);
        float4 xa[6], xc[6];
#pragma unroll
        for (int t = 0; t < 6; t++) {
            xa[t] = xp[t * 64 + lane];
            xc[t] = xp[t * 64 + 32 + lane];
        }
        int mv = (lane < 6) ? mask[bn * 6 + lane] : 0;
        unsigned mb = __ballot_sync(0xffffffffu, mv != 0) & 0x3fu;
        if (lane == 0) ((int*)S)[MB0 + w] = (int)mb;

        float aw[4][6];
#pragma unroll
        for (int h = 0; h < 4; h++) {
            const float4* wf = (const float4*)&S[W0 + h * 256];
            float4 wa = wf[lane], wc = wf[32 + lane];
            float ce = S[W0 + 1024 + h];
            float sc[6];
#pragma unroll
            for (int t = 0; t < 6; t++) {
                float p = xa[t].x * wa.x + xa[t].y * wa.y + xa[t].z * wa.z +
                          xa[t].w * wa.w + xc[t].x * wc.x + xc[t].y * wc.y +
                          xc[t].z * wc.z + xc[t].w * wc.w;
#pragma unroll
                for (int o = 16; o > 0; o >>= 1)
                    p += __shfl_xor_sync(0xffffffffu, p, o);
                sc[t] = ((mb >> t) & 1u) ? (p + ce) * 0.125f : -1e9f;
            }
            float m = sc[0];
#pragma unroll
            for (int t = 1; t < 6; t++) m = fmaxf(m, sc[t]);
            float s = 0.f;
#pragma unroll
            for (int t = 0; t < 6; t++) { aw[h][t] = expf(sc[t] - m); s += aw[h][t]; }
            float inv = 1.0f / s;
#pragma unroll
            for (int t = 0; t < 6; t++) aw[h][t] *= inv;
        }
#pragma unroll
        for (int h = 0; h < 4; h++) {
            float4 A = make_float4(0.f, 0.f, 0.f, 0.f);
            float4 C = make_float4(0.f, 0.f, 0.f, 0.f);
#pragma unroll
            for (int t = 0; t < 6; t++) {
                float a = aw[h][t];
                A.x += a * xa[t].x; A.y += a * xa[t].y;
                A.z += a * xa[t].z; A.w += a * xa[t].w;
                C.x += a * xc[t].x; C.y += a * xc[t].y;
                C.z += a * xc[t].z; C.w += a * xc[t].w;
            }
            uint2 p0 = split_pack2(A.x, A.y), p1 = split_pack2(A.z, A.w);
            uint2 p2 = split_pack2(C.x, C.y), p3 = split_pack2(C.z, C.w);
            int o = w * XSTH + h * 128 + 2 * lane;
            *(uint2*)&XH[o]      = make_uint2(p0.x, p1.x);
            *(uint2*)&XH[o + 64] = make_uint2(p2.x, p3.x);
            *(uint2*)&XL[o]      = make_uint2(p0.y, p1.y);
            *(uint2*)&XL[o + 64] = make_uint2(p2.y, p3.y);
        }
    }
    __syncthreads();

    const int arow = lane & 15;
    const unsigned chunk = ((lane >> 4) & 1) * 16;   // bytes

    // ---- prefetch GEMM2's B tile 0, then GEMM1 (loads its own tile 0) ----
    const uint4* bp2 = g_B2 + (size_t)(wid * 4) * 512 + lane;
    uint4 pre2[4];
#pragma unroll
    for (int nt = 0; nt < 4; nt++) pre2[nt] = __ldg(bp2 + nt * 512);
    {
        const int h = wid >> 1;
        unsigned aHi = sm_u32(XH + arow * XSTH + h * 128) + chunk;
        unsigned aLo = sm_u32(XL + arow * XSTH + h * 128) + chunk;
        gemm_mma<4, 1, false>(aHi, aLo,
                              g_B1 + (size_t)(wid * 4) * 512 + lane, nullptr,
                              &S[BI0], wid * 32, nullptr, 0, BH, BL, BAST);
    }
    __syncthreads();

    // ---- prefetch GEMM3's B tile 0, then GEMM2 (uses pre2) ----
    const uint4* bp3 = g_B3 + (size_t)(wid * 2) * 512 + lane;
    uint4 pre3[2];
#pragma unroll
    for (int nt = 0; nt < 2; nt++) pre3[nt] = __ldg(bp3 + nt * 512);
    {
        unsigned aHi = sm_u32(BH + arow * BAST) + chunk;
        unsigned aLo = sm_u32(BL + arow * BAST) + chunk;
        gemm_mma<4, 0, true>(aHi, aLo, bp2, pre2, &S[BI0 + 256], wid * 32,
                             &S[BB0], BBST, nullptr, nullptr, 0);
    }
    __syncthreads();

    // ---- LayerNorm: bufB fp32 -> bufA (planar). Lane owns 8 consecutive ----
#pragma unroll
    for (int rep = 0; rep < 2; rep++) {
        const int w = wid * 2 + rep;
        float4 va = *(const float4*)&S[BB0 + w * BBST + lane * 8];
        float4 vb = *(const float4*)&S[BB0 + w * BBST + lane * 8 + 4];
        float s = va.x + va.y + va.z + va.w + vb.x + vb.y + vb.z + vb.w;
        float s2 = va.x * va.x + va.y * va.y + va.z * va.z + va.w * va.w +
                   vb.x * vb.x + vb.y * vb.y + vb.z * vb.z + vb.w * vb.w;
#pragma unroll
        for (int o = 16; o > 0; o >>= 1) {
            s  += __shfl_xor_sync(0xffffffffu, s, o);
            s2 += __shfl_xor_sync(0xffffffffu, s2, o);
        }
        float mu = s * (1.0f / 256.0f);
        float var = s2 * (1.0f / 256.0f) - mu * mu;
        float rstd = rsqrtf(var + 1e-5f);
        float y[8];
        float vv[8] = {va.x, va.y, va.z, va.w, vb.x, vb.y, vb.z, vb.w};
#pragma unroll
        for (int j = 0; j < 8; j++) {
            int o = lane * 8 + j;
            y[j] = (vv[j] - mu) * rstd * S[BI0 + 768 + o] + S[BI0 + 1024 + o];
        }
        uint2 p0 = split_pack2(y[0], y[1]), p1 = split_pack2(y[2], y[3]);
        uint2 p2 = split_pack2(y[4], y[5]), p3 = split_pack2(y[6], y[7]);
        *(uint4*)&BH[w * BAST + lane * 4] = make_uint4(p0.x, p1.x, p2.x, p3.x);
        *(uint4*)&BL[w * BAST + lane * 4] = make_uint4(p0.y, p1.y, p2.y, p3.y);
    }
    __syncthreads();

    // ---- GEMM3: fc1 + exact GELU: bufA -> G3 fp32 (uses pre3) ----
    {
        unsigned aHi = sm_u32(BH + arow * BAST) + chunk;
        unsigned aLo = sm_u32(BL + arow * BAST) + chunk;
        gemm_mma<2, 2, true>(aHi, aLo, bp3, pre3, &S[BI0 + 512], wid * 16,
                             &S[G30], G3ST, nullptr, nullptr, 0);
    }
    __syncthreads();

    // ---- Final dot with w2, zero invalid windows ----
#pragma unroll
    for (int rep = 0; rep < 2; rep++) {
        const int w = wid * 2 + rep;
        float r = 0.f;
#pragma unroll
        for (int j = 0; j < 4; j++) {
            int o = lane + 32 * j;
            r += S[G30 + w * G3ST + o] * S[BI0 + 640 + o];
        }
#pragma unroll
        for (int o = 16; o > 0; o >>= 1)
            r += __shfl_xor_sync(0xffffffffu, r, o);
        if (lane == 0) {
            int mb = ((int*)S)[MB0 + w];
            out[bn0 + w] = mb ? (r + S[BI0 + 1280]) : 0.0f;
        }
    }
}

// ---------------------------------------------------------------------------
extern "C" void kernel_launch(void* const* d_in, const int* in_sizes, int n_in,
                              void* d_out, int out_size) {
    (void)in_sizes; (void)n_in; (void)out_size;
    const float* x    = (const float*)d_in[0];
    const int*   mask = (const int*)d_in[1];
    const float* query= (const float*)d_in[2];
    const float* ipw  = (const float*)d_in[3];
    const float* ipb  = (const float*)d_in[4];
    const float* outw = (const float*)d_in[5];
    const float* outb = (const float*)d_in[6];
    const float* ln_g = (const float*)d_in[7];
    const float* ln_b = (const float*)d_in[8];
    const float* w1   = (const float*)d_in[9];
    const float* b1   = (const float*)d_in[10];
    const float* w2   = (const float*)d_in[11];
    const float* b2   = (const float*)d_in[12];
    float* out = (float*)d_out;

    cudaFuncSetAttribute(ach_main, cudaFuncAttributeMaxDynamicSharedMemorySize,
                         SMEM_BYTES);

    ach_prepA<<<192, 256>>>(query, ipw, ipb, outw, w1);
    ach_prepB<<<4, 256>>>(ipw, ipb);
    ach_main<<<2048, 256, SMEM_BYTES>>>(x, mask, ipb, outb, ln_g, ln_b, b1, w2,
                                        b2, out);
}